// round 16
// baseline (speedup 1.0000x reference)
#include <cuda_runtime.h>
#include <cuda_fp16.h>
#include <cstdint>

// ============================================================================
// QATLinear: y[t,o] = scale[o] * sum_i x[t,i]*sign(w[o,i]) + b[o]
//
// sign(W)=+-1 exact in fp16; x as fp16, fp32 mma.sync accumulation.
// R16 = R15 (best: 2328us; GEMM tensor=80.4%, stable 4 rounds) + ONE change:
// epilogue output stores use st.global.cs (evict-first). The 512MB output
// stream is never re-read; default write-allocate was displacing A/B tiles
// in L2 that the GROUP_M swizzle re-hits from neighbor CTAs.
// GEMM inner loop byte-identical. Config: BM=BN=128, BK=64, 8 warps (32x64
// tile), STAGES=3, 2 CTAs/SM, one barrier/chunk, k-phase stagger, kh fragment
// double buffering, smem-prefetched scale/bias, MLP=4 prep (single launch).
// ============================================================================

#define TOKENS 8192
#define DIN    4096
#define DOUT   16384

static constexpr int BM = 128;
static constexpr int BN = 128;
static constexpr int BK = 64;
static constexpr int STAGES = 3;
static constexpr int THREADS = 256;              // 8 warps: 4 (m) x 2 (n)
static constexpr int NCHUNK = DIN / BK;          // 64

static constexpr int A_STAGE_B = BM * BK * 2;    // 16384 B
static constexpr int B_STAGE_B = BN * BK * 2;    // 16384 B
static constexpr int STAGE_B   = A_STAGE_B + B_STAGE_B;   // 32768
static constexpr int SCB_OFF   = STAGES * STAGE_B;        // 98304
static constexpr int SMEM_TOTAL = SCB_OFF + 1024;         // 99328 per CTA

// ---- scratch (device globals: allocation-free rule) ----
__device__ __half g_A [(size_t)TOKENS * DIN];    // 64 MB  (x as fp16)
__device__ __half g_Bs[(size_t)DOUT  * DIN];     // 128 MB (sign(w) as fp16)

// ============================ PTX helpers ===================================
__device__ __forceinline__ uint32_t smem_u32(const void* p) {
    uint32_t a;
    asm("{ .reg .u64 t; cvta.to.shared.u64 t, %1; cvt.u32.u64 %0, t; }"
        : "=r"(a) : "l"(p));
    return a;
}
__device__ __forceinline__ void cp_async16(uint32_t saddr, const void* gptr) {
    asm volatile("cp.async.cg.shared.global [%0], [%1], 16;"
                 :: "r"(saddr), "l"(gptr) : "memory");
}
__device__ __forceinline__ void cp_commit() {
    asm volatile("cp.async.commit_group;" ::: "memory");
}
template <int N>
__device__ __forceinline__ void cp_wait() {
    asm volatile("cp.async.wait_group %0;" :: "n"(N) : "memory");
}
__device__ __forceinline__ void ldmatrix_x4(uint32_t& r0, uint32_t& r1,
                                            uint32_t& r2, uint32_t& r3,
                                            uint32_t addr) {
    asm volatile("ldmatrix.sync.aligned.m8n8.x4.shared.b16 {%0,%1,%2,%3}, [%4];"
                 : "=r"(r0), "=r"(r1), "=r"(r2), "=r"(r3) : "r"(addr));
}
__device__ __forceinline__ void mma_16816(float* c, const uint32_t* a,
                                          const uint32_t* b) {
    asm volatile(
        "mma.sync.aligned.m16n8k16.row.col.f32.f16.f16.f32 "
        "{%0,%1,%2,%3}, {%4,%5,%6,%7}, {%8,%9}, {%0,%1,%2,%3};"
        : "+f"(c[0]), "+f"(c[1]), "+f"(c[2]), "+f"(c[3])
        : "r"(a[0]), "r"(a[1]), "r"(a[2]), "r"(a[3]), "r"(b[0]), "r"(b[1]));
}
__device__ __forceinline__ void stg_cs_v4(void* p, uint32_t a, uint32_t b,
                                          uint32_t c, uint32_t d) {
    asm volatile("st.global.cs.v4.u32 [%0], {%1, %2, %3, %4};"
                 :: "l"(p), "r"(a), "r"(b), "r"(c), "r"(d) : "memory");
}
__device__ __forceinline__ void stg_cs_f2(void* p, float2 v) {
    asm volatile("st.global.cs.v2.f32 [%0], {%1, %2};"
                 :: "l"(p), "f"(v.x), "f"(v.y) : "memory");
}
// tile rows: 64 fp16 = 128 B = 8 x 16B chunks; chunk' = chunk ^ (row&7)
__device__ __forceinline__ uint32_t sw_off(int row, int chunk) {
    return (uint32_t)((row << 7) + ((chunk ^ (row & 7)) << 4));
}

// ===================== fused prep kernel (one launch) =======================
// each thread: 4 independent float4 loads (MLP=4) -> 2 x 16B cs stores
static constexpr size_t A_F4 = (size_t)TOKENS * DIN / 4;   // 2^23
static constexpr size_t B_F4 = (size_t)DOUT  * DIN / 4;    // 2^24
static constexpr unsigned PREP_NA = (unsigned)(A_F4 / (4 * 256));  // 8192
static constexpr unsigned PREP_NB = (unsigned)(B_F4 / (4 * 256));  // 16384

__device__ __forceinline__ uint2 cvt_a(float4 v) {
    uint32_t h0 = __half_as_ushort(__float2half_rn(v.x))
                | ((uint32_t)__half_as_ushort(__float2half_rn(v.y)) << 16);
    uint32_t h1 = __half_as_ushort(__float2half_rn(v.z))
                | ((uint32_t)__half_as_ushort(__float2half_rn(v.w)) << 16);
    uint2 p; p.x = h0; p.y = h1; return p;
}
__device__ __forceinline__ uint2 cvt_b(float4 v) {
    // sign with 0 -> +1 ; fp16 +1.0 = 0x3C00, -1.0 = 0xBC00
    uint32_t s0 = (v.x >= 0.0f) ? 0x3C00u : 0xBC00u;
    uint32_t s1 = (v.y >= 0.0f) ? 0x3C00u : 0xBC00u;
    uint32_t s2 = (v.z >= 0.0f) ? 0x3C00u : 0xBC00u;
    uint32_t s3 = (v.w >= 0.0f) ? 0x3C00u : 0xBC00u;
    uint2 p; p.x = s0 | (s1 << 16); p.y = s2 | (s3 << 16); return p;
}

__global__ void prep_fused_kernel(const float* __restrict__ x,
                                  const float* __restrict__ w) {
    const unsigned b = blockIdx.x;
    if (b < PREP_NA) {
        const size_t i0 = ((size_t)b * blockDim.x + threadIdx.x) * 4;
        float4 v0 = __ldg((const float4*)x + i0);
        float4 v1 = __ldg((const float4*)x + i0 + 1);
        float4 v2 = __ldg((const float4*)x + i0 + 2);
        float4 v3 = __ldg((const float4*)x + i0 + 3);
        uint2 p0 = cvt_a(v0), p1 = cvt_a(v1), p2 = cvt_a(v2), p3 = cvt_a(v3);
        stg_cs_v4((uint2*)g_A + i0,     p0.x, p0.y, p1.x, p1.y);
        stg_cs_v4((uint2*)g_A + i0 + 2, p2.x, p2.y, p3.x, p3.y);
    } else {
        const size_t i0 = ((size_t)(b - PREP_NA) * blockDim.x + threadIdx.x) * 4;
        float4 v0 = __ldg((const float4*)w + i0);
        float4 v1 = __ldg((const float4*)w + i0 + 1);
        float4 v2 = __ldg((const float4*)w + i0 + 2);
        float4 v3 = __ldg((const float4*)w + i0 + 3);
        uint2 p0 = cvt_b(v0), p1 = cvt_b(v1), p2 = cvt_b(v2), p3 = cvt_b(v3);
        stg_cs_v4((uint2*)g_Bs + i0,     p0.x, p0.y, p1.x, p1.y);
        stg_cs_v4((uint2*)g_Bs + i0 + 2, p2.x, p2.y, p3.x, p3.y);
    }
}

// ============================ GEMM kernel ===================================
__global__ void __launch_bounds__(THREADS, 2)
qat_gemm_kernel(const float* __restrict__ scale, const float* __restrict__ bias,
                float* __restrict__ out) {
    extern __shared__ char smem[];
    const uint32_t sbase = smem_u32(smem);
    const int tid  = threadIdx.x;
    const int wid  = tid >> 5;
    const int lane = tid & 31;

    // grouped tile swizzle (GROUP_M = 8): 64 m-tiles x 128 n-tiles
    const int pid   = blockIdx.x;                 // 0 .. 8191
    const int group = pid >> 10;
    const int inb   = pid & 1023;
    const int pid_m = (group << 3) + (inb & 7);
    const int pid_n = inb >> 3;
    const int m0 = pid_m * BM;
    const int n0 = pid_n * BN;

    // phase stagger: wave partners anti-align k-loops
    const int coff = ((pid / 148) & 1) ? (NCHUNK / 2) : 0;

    // warp tile: 32 (m) x 64 (n); warps: 4 (m) x 2 (n)
    const int warp_m = wid & 3;
    const int warp_n = wid >> 2;
    const int wm0 = warp_m * 32;
    const int wn0 = warp_n * 64;

    // ---- global load indices (16B per cp.async; rows are 8x16B chunks) ----
    const int g_row = tid >> 3;               // 0..31
    const int g_chk = tid & 7;

    const __half* gA0 = g_A  + (size_t)(m0 + g_row) * DIN + g_chk * 8;
    const __half* gA1 = gA0 + (size_t)32 * DIN;
    const __half* gA2 = gA0 + (size_t)64 * DIN;
    const __half* gA3 = gA0 + (size_t)96 * DIN;
    const __half* gB0 = g_Bs + (size_t)(n0 + g_row) * DIN + g_chk * 8;
    const __half* gB1 = gB0 + (size_t)32 * DIN;
    const __half* gB2 = gB0 + (size_t)64 * DIN;
    const __half* gB3 = gB0 + (size_t)96 * DIN;

    const uint32_t sO0 = sw_off(g_row,      g_chk);
    const uint32_t sO1 = sw_off(g_row + 32, g_chk);
    const uint32_t sO2 = sw_off(g_row + 64, g_chk);
    const uint32_t sO3 = sw_off(g_row + 96, g_chk);

    auto issue_stage = [&](int cc) {
        const int s = cc % STAGES;
        const int c = (cc + coff) & (NCHUNK - 1);
        const uint32_t stA = sbase + s * STAGE_B;
        const uint32_t stB = stA + A_STAGE_B;
        const size_t kofs = (size_t)c * BK;
        cp_async16(stA + sO0, gA0 + kofs);
        cp_async16(stA + sO1, gA1 + kofs);
        cp_async16(stA + sO2, gA2 + kofs);
        cp_async16(stA + sO3, gA3 + kofs);
        cp_async16(stB + sO0, gB0 + kofs);
        cp_async16(stB + sO1, gB1 + kofs);
        cp_async16(stB + sO2, gB2 + kofs);
        cp_async16(stB + sO3, gB3 + kofs);
    };

    // ---- prologue: scale/bias prefetch bundled with stage 0's group ----
    if (tid < 32)       cp_async16(sbase + SCB_OFF + tid * 16,
                                   scale + n0 + tid * 4);
    else if (tid < 64)  cp_async16(sbase + SCB_OFF + 512 + (tid - 32) * 16,
                                   bias + n0 + (tid - 32) * 4);
    issue_stage(0); cp_commit();
#pragma unroll
    for (int cc = 1; cc < STAGES - 1; ++cc) { issue_stage(cc); cp_commit(); }

    // ---- accumulators: 2 m-frags x 8 n-frags x 4 ----
    float acc[2][8][4];
#pragma unroll
    for (int i = 0; i < 2; ++i)
#pragma unroll
        for (int j = 0; j < 8; ++j)
#pragma unroll
            for (int q = 0; q < 4; ++q) acc[i][j][q] = 0.0f;

    const int lquad = lane >> 3;
    const int lrow  = lane & 7;

#pragma unroll 1
    for (int cc = 0; cc < NCHUNK; ++cc) {
        cp_wait<STAGES - 2>();
        __syncthreads();   // all warps done reading slot cc-1

        const uint32_t stA = sbase + (cc % STAGES) * STAGE_B;
        const uint32_t stB = stA + A_STAGE_B;

        // ---- kh=0 fragment loads FIRST (refill tensor stream immediately) --
        uint32_t afr[2][4];
        uint32_t bfr[8][2];
#pragma unroll
        for (int mi = 0; mi < 2; ++mi) {
            int row = wm0 + mi * 16 + lrow + ((lquad & 1) << 3);
            int chk = (lquad >> 1);
            ldmatrix_x4(afr[mi][0], afr[mi][1], afr[mi][2], afr[mi][3],
                        stA + sw_off(row, chk));
        }
#pragma unroll
        for (int jp = 0; jp < 4; ++jp) {
            int row = wn0 + jp * 16 + lrow + ((lquad >> 1) << 3);
            int chk = (lquad & 1);
            uint32_t r0, r1, r2, r3;
            ldmatrix_x4(r0, r1, r2, r3, stB + sw_off(row, chk));
            bfr[jp * 2 + 0][0] = r0; bfr[jp * 2 + 0][1] = r1;
            bfr[jp * 2 + 1][0] = r2; bfr[jp * 2 + 1][1] = r3;
        }

        // next-stage cp.asyncs AFTER the first fragment batch
        if (cc + STAGES - 1 < NCHUNK) issue_stage(cc + STAGES - 1);
        cp_commit();

#pragma unroll
        for (int kh = 0; kh < 4; ++kh) {      // four k16 halves of BK=64
            // MMAs on current fragments
#pragma unroll
            for (int mi = 0; mi < 2; ++mi)
#pragma unroll
                for (int j = 0; j < 8; ++j)
                    mma_16816(acc[mi][j], afr[mi], bfr[j]);

            // load kh+1 fragments (skipped on last kh)
            if (kh < 3) {
                const int kchunk = (kh + 1) * 2;
#pragma unroll
                for (int mi = 0; mi < 2; ++mi) {
                    int row = wm0 + mi * 16 + lrow + ((lquad & 1) << 3);
                    int chk = kchunk + (lquad >> 1);
                    ldmatrix_x4(afr[mi][0], afr[mi][1], afr[mi][2], afr[mi][3],
                                stA + sw_off(row, chk));
                }
#pragma unroll
                for (int jp = 0; jp < 4; ++jp) {
                    int row = wn0 + jp * 16 + lrow + ((lquad >> 1) << 3);
                    int chk = kchunk + (lquad & 1);
                    uint32_t r0, r1, r2, r3;
                    ldmatrix_x4(r0, r1, r2, r3, stB + sw_off(row, chk));
                    bfr[jp * 2 + 0][0] = r0; bfr[jp * 2 + 0][1] = r1;
                    bfr[jp * 2 + 1][0] = r2; bfr[jp * 2 + 1][1] = r3;
                }
            }
        }
    }

    // ---- epilogue: scale/bias from smem; evict-first (cs) output stores ----
    const int tq = lane >> 2;
    const int tr = lane & 3;
    const float* sc_s = (const float*)(smem + SCB_OFF);
    const float* bb_s = (const float*)(smem + SCB_OFF + 512);
#pragma unroll
    for (int j = 0; j < 8; ++j) {
        const int col = wn0 + j * 8 + 2 * tr;        // 0..127 within tile
        const int n = n0 + col;
        const float2 sc = *(const float2*)(sc_s + col);
        const float2 bb = *(const float2*)(bb_s + col);
#pragma unroll
        for (int mi = 0; mi < 2; ++mi) {
            const int mrow = m0 + wm0 + mi * 16 + tq;
            float2 v0, v1;
            v0.x = fmaf(sc.x, acc[mi][j][0], bb.x);
            v0.y = fmaf(sc.y, acc[mi][j][1], bb.y);
            v1.x = fmaf(sc.x, acc[mi][j][2], bb.x);
            v1.y = fmaf(sc.y, acc[mi][j][3], bb.y);
            stg_cs_f2(out + (size_t)mrow * DOUT + n, v0);
            stg_cs_f2(out + (size_t)(mrow + 8) * DOUT + n, v1);
        }
    }
}

// ============================ launch ========================================
extern "C" void kernel_launch(void* const* d_in, const int* in_sizes, int n_in,
                              void* d_out, int out_size) {
    (void)in_sizes; (void)n_in; (void)out_size;
    const float* x     = (const float*)d_in[0];
    const float* w     = (const float*)d_in[1];
    const float* scale = (const float*)d_in[2];
    const float* b     = (const float*)d_in[3];
    float* out = (float*)d_out;

    prep_fused_kernel<<<PREP_NA + PREP_NB, 256>>>(x, w);

    cudaFuncSetAttribute(qat_gemm_kernel,
                         cudaFuncAttributeMaxDynamicSharedMemorySize,
                         SMEM_TOTAL);
    const int grid = (TOKENS / BM) * (DOUT / BN);   // 8192
    qat_gemm_kernel<<<grid, THREADS, SMEM_TOTAL>>>(scale, b, out);
}

// round 17
// speedup vs baseline: 1.0009x; 1.0009x over previous
#include <cuda_runtime.h>
#include <cuda_fp16.h>
#include <cstdint>

// ============================================================================
// QATLinear: y[t,o] = scale[o] * sum_i x[t,i]*sign(w[o,i]) + b[o]
//
// sign(W)=+-1 exact in fp16; x as fp16, fp32 mma.sync accumulation.
// R17 = R15 (best: 2327.6us; R16's evict-first stores were neutral ->
// reverted to plain stores) + ONE untested knob: GROUP_M 8 -> 16 in the tile
// swizzle, squaring the per-wave L2 working set (A 8MB+B 38MB -> 16MB+19MB).
// Outside the hot loop; zero register/schedule risk.
// GEMM config (frozen by 4 rounds of stable ncu evidence): BM=BN=128, BK=64,
// 8 warps (32x64 tile), STAGES=3, 2 CTAs/SM, one barrier/chunk, k-phase
// stagger, kh fragment double buffering, smem-prefetched scale/bias,
// MLP=4 single-launch prep.
// ============================================================================

#define TOKENS 8192
#define DIN    4096
#define DOUT   16384

static constexpr int BM = 128;
static constexpr int BN = 128;
static constexpr int BK = 64;
static constexpr int STAGES = 3;
static constexpr int THREADS = 256;              // 8 warps: 4 (m) x 2 (n)
static constexpr int NCHUNK = DIN / BK;          // 64

static constexpr int A_STAGE_B = BM * BK * 2;    // 16384 B
static constexpr int B_STAGE_B = BN * BK * 2;    // 16384 B
static constexpr int STAGE_B   = A_STAGE_B + B_STAGE_B;   // 32768
static constexpr int SCB_OFF   = STAGES * STAGE_B;        // 98304
static constexpr int SMEM_TOTAL = SCB_OFF + 1024;         // 99328 per CTA

// ---- scratch (device globals: allocation-free rule) ----
__device__ __half g_A [(size_t)TOKENS * DIN];    // 64 MB  (x as fp16)
__device__ __half g_Bs[(size_t)DOUT  * DIN];     // 128 MB (sign(w) as fp16)

// ============================ PTX helpers ===================================
__device__ __forceinline__ uint32_t smem_u32(const void* p) {
    uint32_t a;
    asm("{ .reg .u64 t; cvta.to.shared.u64 t, %1; cvt.u32.u64 %0, t; }"
        : "=r"(a) : "l"(p));
    return a;
}
__device__ __forceinline__ void cp_async16(uint32_t saddr, const void* gptr) {
    asm volatile("cp.async.cg.shared.global [%0], [%1], 16;"
                 :: "r"(saddr), "l"(gptr) : "memory");
}
__device__ __forceinline__ void cp_commit() {
    asm volatile("cp.async.commit_group;" ::: "memory");
}
template <int N>
__device__ __forceinline__ void cp_wait() {
    asm volatile("cp.async.wait_group %0;" :: "n"(N) : "memory");
}
__device__ __forceinline__ void ldmatrix_x4(uint32_t& r0, uint32_t& r1,
                                            uint32_t& r2, uint32_t& r3,
                                            uint32_t addr) {
    asm volatile("ldmatrix.sync.aligned.m8n8.x4.shared.b16 {%0,%1,%2,%3}, [%4];"
                 : "=r"(r0), "=r"(r1), "=r"(r2), "=r"(r3) : "r"(addr));
}
__device__ __forceinline__ void mma_16816(float* c, const uint32_t* a,
                                          const uint32_t* b) {
    asm volatile(
        "mma.sync.aligned.m16n8k16.row.col.f32.f16.f16.f32 "
        "{%0,%1,%2,%3}, {%4,%5,%6,%7}, {%8,%9}, {%0,%1,%2,%3};"
        : "+f"(c[0]), "+f"(c[1]), "+f"(c[2]), "+f"(c[3])
        : "r"(a[0]), "r"(a[1]), "r"(a[2]), "r"(a[3]), "r"(b[0]), "r"(b[1]));
}
__device__ __forceinline__ void stg_cs_v4(void* p, uint32_t a, uint32_t b,
                                          uint32_t c, uint32_t d) {
    asm volatile("st.global.cs.v4.u32 [%0], {%1, %2, %3, %4};"
                 :: "l"(p), "r"(a), "r"(b), "r"(c), "r"(d) : "memory");
}
// tile rows: 64 fp16 = 128 B = 8 x 16B chunks; chunk' = chunk ^ (row&7)
__device__ __forceinline__ uint32_t sw_off(int row, int chunk) {
    return (uint32_t)((row << 7) + ((chunk ^ (row & 7)) << 4));
}

// ===================== fused prep kernel (one launch) =======================
// each thread: 4 independent float4 loads (MLP=4) -> 2 x 16B cs stores
static constexpr size_t A_F4 = (size_t)TOKENS * DIN / 4;   // 2^23
static constexpr size_t B_F4 = (size_t)DOUT  * DIN / 4;    // 2^24
static constexpr unsigned PREP_NA = (unsigned)(A_F4 / (4 * 256));  // 8192
static constexpr unsigned PREP_NB = (unsigned)(B_F4 / (4 * 256));  // 16384

__device__ __forceinline__ uint2 cvt_a(float4 v) {
    uint32_t h0 = __half_as_ushort(__float2half_rn(v.x))
                | ((uint32_t)__half_as_ushort(__float2half_rn(v.y)) << 16);
    uint32_t h1 = __half_as_ushort(__float2half_rn(v.z))
                | ((uint32_t)__half_as_ushort(__float2half_rn(v.w)) << 16);
    uint2 p; p.x = h0; p.y = h1; return p;
}
__device__ __forceinline__ uint2 cvt_b(float4 v) {
    // sign with 0 -> +1 ; fp16 +1.0 = 0x3C00, -1.0 = 0xBC00
    uint32_t s0 = (v.x >= 0.0f) ? 0x3C00u : 0xBC00u;
    uint32_t s1 = (v.y >= 0.0f) ? 0x3C00u : 0xBC00u;
    uint32_t s2 = (v.z >= 0.0f) ? 0x3C00u : 0xBC00u;
    uint32_t s3 = (v.w >= 0.0f) ? 0x3C00u : 0xBC00u;
    uint2 p; p.x = s0 | (s1 << 16); p.y = s2 | (s3 << 16); return p;
}

__global__ void prep_fused_kernel(const float* __restrict__ x,
                                  const float* __restrict__ w) {
    const unsigned b = blockIdx.x;
    if (b < PREP_NA) {
        const size_t i0 = ((size_t)b * blockDim.x + threadIdx.x) * 4;
        float4 v0 = __ldg((const float4*)x + i0);
        float4 v1 = __ldg((const float4*)x + i0 + 1);
        float4 v2 = __ldg((const float4*)x + i0 + 2);
        float4 v3 = __ldg((const float4*)x + i0 + 3);
        uint2 p0 = cvt_a(v0), p1 = cvt_a(v1), p2 = cvt_a(v2), p3 = cvt_a(v3);
        stg_cs_v4((uint2*)g_A + i0,     p0.x, p0.y, p1.x, p1.y);
        stg_cs_v4((uint2*)g_A + i0 + 2, p2.x, p2.y, p3.x, p3.y);
    } else {
        const size_t i0 = ((size_t)(b - PREP_NA) * blockDim.x + threadIdx.x) * 4;
        float4 v0 = __ldg((const float4*)w + i0);
        float4 v1 = __ldg((const float4*)w + i0 + 1);
        float4 v2 = __ldg((const float4*)w + i0 + 2);
        float4 v3 = __ldg((const float4*)w + i0 + 3);
        uint2 p0 = cvt_b(v0), p1 = cvt_b(v1), p2 = cvt_b(v2), p3 = cvt_b(v3);
        stg_cs_v4((uint2*)g_Bs + i0,     p0.x, p0.y, p1.x, p1.y);
        stg_cs_v4((uint2*)g_Bs + i0 + 2, p2.x, p2.y, p3.x, p3.y);
    }
}

// ============================ GEMM kernel ===================================
__global__ void __launch_bounds__(THREADS, 2)
qat_gemm_kernel(const float* __restrict__ scale, const float* __restrict__ bias,
                float* __restrict__ out) {
    extern __shared__ char smem[];
    const uint32_t sbase = smem_u32(smem);
    const int tid  = threadIdx.x;
    const int wid  = tid >> 5;
    const int lane = tid & 31;

    // grouped tile swizzle (GROUP_M = 16): 64 m-tiles x 128 n-tiles
    const int pid   = blockIdx.x;                 // 0 .. 8191
    const int group = pid >> 11;                  // / (16*128)
    const int inb   = pid & 2047;
    const int pid_m = (group << 4) + (inb & 15);
    const int pid_n = inb >> 4;
    const int m0 = pid_m * BM;
    const int n0 = pid_n * BN;

    // phase stagger: wave partners anti-align k-loops
    const int coff = ((pid / 148) & 1) ? (NCHUNK / 2) : 0;

    // warp tile: 32 (m) x 64 (n); warps: 4 (m) x 2 (n)
    const int warp_m = wid & 3;
    const int warp_n = wid >> 2;
    const int wm0 = warp_m * 32;
    const int wn0 = warp_n * 64;

    // ---- global load indices (16B per cp.async; rows are 8x16B chunks) ----
    const int g_row = tid >> 3;               // 0..31
    const int g_chk = tid & 7;

    const __half* gA0 = g_A  + (size_t)(m0 + g_row) * DIN + g_chk * 8;
    const __half* gA1 = gA0 + (size_t)32 * DIN;
    const __half* gA2 = gA0 + (size_t)64 * DIN;
    const __half* gA3 = gA0 + (size_t)96 * DIN;
    const __half* gB0 = g_Bs + (size_t)(n0 + g_row) * DIN + g_chk * 8;
    const __half* gB1 = gB0 + (size_t)32 * DIN;
    const __half* gB2 = gB0 + (size_t)64 * DIN;
    const __half* gB3 = gB0 + (size_t)96 * DIN;

    const uint32_t sO0 = sw_off(g_row,      g_chk);
    const uint32_t sO1 = sw_off(g_row + 32, g_chk);
    const uint32_t sO2 = sw_off(g_row + 64, g_chk);
    const uint32_t sO3 = sw_off(g_row + 96, g_chk);

    auto issue_stage = [&](int cc) {
        const int s = cc % STAGES;
        const int c = (cc + coff) & (NCHUNK - 1);
        const uint32_t stA = sbase + s * STAGE_B;
        const uint32_t stB = stA + A_STAGE_B;
        const size_t kofs = (size_t)c * BK;
        cp_async16(stA + sO0, gA0 + kofs);
        cp_async16(stA + sO1, gA1 + kofs);
        cp_async16(stA + sO2, gA2 + kofs);
        cp_async16(stA + sO3, gA3 + kofs);
        cp_async16(stB + sO0, gB0 + kofs);
        cp_async16(stB + sO1, gB1 + kofs);
        cp_async16(stB + sO2, gB2 + kofs);
        cp_async16(stB + sO3, gB3 + kofs);
    };

    // ---- prologue: scale/bias prefetch bundled with stage 0's group ----
    if (tid < 32)       cp_async16(sbase + SCB_OFF + tid * 16,
                                   scale + n0 + tid * 4);
    else if (tid < 64)  cp_async16(sbase + SCB_OFF + 512 + (tid - 32) * 16,
                                   bias + n0 + (tid - 32) * 4);
    issue_stage(0); cp_commit();
#pragma unroll
    for (int cc = 1; cc < STAGES - 1; ++cc) { issue_stage(cc); cp_commit(); }

    // ---- accumulators: 2 m-frags x 8 n-frags x 4 ----
    float acc[2][8][4];
#pragma unroll
    for (int i = 0; i < 2; ++i)
#pragma unroll
        for (int j = 0; j < 8; ++j)
#pragma unroll
            for (int q = 0; q < 4; ++q) acc[i][j][q] = 0.0f;

    const int lquad = lane >> 3;
    const int lrow  = lane & 7;

#pragma unroll 1
    for (int cc = 0; cc < NCHUNK; ++cc) {
        cp_wait<STAGES - 2>();
        __syncthreads();   // all warps done reading slot cc-1

        const uint32_t stA = sbase + (cc % STAGES) * STAGE_B;
        const uint32_t stB = stA + A_STAGE_B;

        // ---- kh=0 fragment loads FIRST (refill tensor stream immediately) --
        uint32_t afr[2][4];
        uint32_t bfr[8][2];
#pragma unroll
        for (int mi = 0; mi < 2; ++mi) {
            int row = wm0 + mi * 16 + lrow + ((lquad & 1) << 3);
            int chk = (lquad >> 1);
            ldmatrix_x4(afr[mi][0], afr[mi][1], afr[mi][2], afr[mi][3],
                        stA + sw_off(row, chk));
        }
#pragma unroll
        for (int jp = 0; jp < 4; ++jp) {
            int row = wn0 + jp * 16 + lrow + ((lquad >> 1) << 3);
            int chk = (lquad & 1);
            uint32_t r0, r1, r2, r3;
            ldmatrix_x4(r0, r1, r2, r3, stB + sw_off(row, chk));
            bfr[jp * 2 + 0][0] = r0; bfr[jp * 2 + 0][1] = r1;
            bfr[jp * 2 + 1][0] = r2; bfr[jp * 2 + 1][1] = r3;
        }

        // next-stage cp.asyncs AFTER the first fragment batch
        if (cc + STAGES - 1 < NCHUNK) issue_stage(cc + STAGES - 1);
        cp_commit();

#pragma unroll
        for (int kh = 0; kh < 4; ++kh) {      // four k16 halves of BK=64
            // MMAs on current fragments
#pragma unroll
            for (int mi = 0; mi < 2; ++mi)
#pragma unroll
                for (int j = 0; j < 8; ++j)
                    mma_16816(acc[mi][j], afr[mi], bfr[j]);

            // load kh+1 fragments (skipped on last kh)
            if (kh < 3) {
                const int kchunk = (kh + 1) * 2;
#pragma unroll
                for (int mi = 0; mi < 2; ++mi) {
                    int row = wm0 + mi * 16 + lrow + ((lquad & 1) << 3);
                    int chk = kchunk + (lquad >> 1);
                    ldmatrix_x4(afr[mi][0], afr[mi][1], afr[mi][2], afr[mi][3],
                                stA + sw_off(row, chk));
                }
#pragma unroll
                for (int jp = 0; jp < 4; ++jp) {
                    int row = wn0 + jp * 16 + lrow + ((lquad >> 1) << 3);
                    int chk = kchunk + (lquad & 1);
                    uint32_t r0, r1, r2, r3;
                    ldmatrix_x4(r0, r1, r2, r3, stB + sw_off(row, chk));
                    bfr[jp * 2 + 0][0] = r0; bfr[jp * 2 + 0][1] = r1;
                    bfr[jp * 2 + 1][0] = r2; bfr[jp * 2 + 1][1] = r3;
                }
            }
        }
    }

    // ---- epilogue: scale/bias from smem (prefetched), float2 stores ----
    const int tq = lane >> 2;
    const int tr = lane & 3;
    const float* sc_s = (const float*)(smem + SCB_OFF);
    const float* bb_s = (const float*)(smem + SCB_OFF + 512);
#pragma unroll
    for (int j = 0; j < 8; ++j) {
        const int col = wn0 + j * 8 + 2 * tr;        // 0..127 within tile
        const int n = n0 + col;
        const float2 sc = *(const float2*)(sc_s + col);
        const float2 bb = *(const float2*)(bb_s + col);
#pragma unroll
        for (int mi = 0; mi < 2; ++mi) {
            const int mrow = m0 + wm0 + mi * 16 + tq;
            float2 v0, v1;
            v0.x = fmaf(sc.x, acc[mi][j][0], bb.x);
            v0.y = fmaf(sc.y, acc[mi][j][1], bb.y);
            v1.x = fmaf(sc.x, acc[mi][j][2], bb.x);
            v1.y = fmaf(sc.y, acc[mi][j][3], bb.y);
            *(float2*)(out + (size_t)mrow * DOUT + n) = v0;
            *(float2*)(out + (size_t)(mrow + 8) * DOUT + n) = v1;
        }
    }
}

// ============================ launch ========================================
extern "C" void kernel_launch(void* const* d_in, const int* in_sizes, int n_in,
                              void* d_out, int out_size) {
    (void)in_sizes; (void)n_in; (void)out_size;
    const float* x     = (const float*)d_in[0];
    const float* w     = (const float*)d_in[1];
    const float* scale = (const float*)d_in[2];
    const float* b     = (const float*)d_in[3];
    float* out = (float*)d_out;

    prep_fused_kernel<<<PREP_NA + PREP_NB, 256>>>(x, w);

    cudaFuncSetAttribute(qat_gemm_kernel,
                         cudaFuncAttributeMaxDynamicSharedMemorySize,
                         SMEM_TOTAL);
    const int grid = (TOKENS / BM) * (DOUT / BN);   // 8192
    qat_gemm_kernel<<<grid, THREADS, SMEM_TOTAL>>>(scale, b, out);
}